// round 9
// baseline (speedup 1.0000x reference)
#include <cuda_runtime.h>
#include <cuda_bf16.h>
#include <cstdint>

// ---------------------------------------------------------------------------
// EdgeAlignmentModule — generation-tagged hash join, 2 launches, no reset,
// 4 edges per thread (phase-batched loads for MLP).
//
//   key(src,dst) = src * total_nodes + dst   (< 1e8, fits in 27 bits)
//   Slot word (64b) = gen(18) << 46 | key(27) << 19 | idx(19)
//
// Slot with gen field != current gen is EMPTY (stale); claimed by CAS against
// the observed stale word. Duplicate keys within a call -> MAX old index
// (matches sequential-scatter "last wins") via atomicMax: equal (gen,key)
// orders by idx. Per-call gen derived on-device from a per-kernel counter
// (one bump per block; stream ordering partitions arrivals per call).
// Table starts zeroed (gen 0); first call uses gen 1.
// ---------------------------------------------------------------------------

#define TABLE_LOG2 20
#define TABLE_SIZE (1u << TABLE_LOG2)
#define TABLE_MASK (TABLE_SIZE - 1u)

#define GEN_SHIFT 46
#define KEY_SHIFT 19
#define IDX_MASK  ((1u << KEY_SHIFT) - 1u)

#define NTHREADS 256
#define BATCH 4
#define CHUNK (NTHREADS * BATCH)   // edges per block

__device__ unsigned long long g_tab[TABLE_SIZE];   // zero-init: gen 0 = stale
__device__ unsigned long long g_ctr_ins;           // insert call counter
__device__ unsigned long long g_ctr_lkp;           // lookup call counter

__device__ __forceinline__ uint32_t hash_key(uint32_t key) {
    return (key * 0x9E3779B1u) >> (32 - TABLE_LOG2);
}

__device__ __forceinline__ unsigned long long
block_gen(unsigned long long* ctr) {
    __shared__ unsigned long long s_gen;
    if (threadIdx.x == 0) {
        unsigned long long t = atomicAdd(ctr, 1ull);
        s_gen = t / gridDim.x + 1ull;   // same value for every block of a call
    }
    __syncthreads();
    return s_gen;
}

// ---- Kernel 1: insert old edges (4/thread, batched loads) ------------------
__global__ __launch_bounds__(NTHREADS)
void insert_kernel(const int* __restrict__ edge_index_old,
                   int E_old, int total_nodes) {
    const unsigned long long gen = block_gen(&g_ctr_ins);
    const int base = blockIdx.x * CHUNK + threadIdx.x;

    int      src[BATCH], dst[BATCH];
    uint32_t key[BATCH], h[BATCH];
    unsigned long long w0[BATCH];

    // Phase A: batch coalesced index loads (independent -> overlapped).
    #pragma unroll
    for (int k = 0; k < BATCH; k++) {
        int i = base + k * NTHREADS;
        if (i < E_old) src[k] = __ldg(edge_index_old + i);
    }
    #pragma unroll
    for (int k = 0; k < BATCH; k++) {
        int i = base + k * NTHREADS;
        if (i < E_old) dst[k] = __ldg(edge_index_old + E_old + i);
    }
    // Phase B: keys + batch first-probe loads (independent scattered LDGs).
    #pragma unroll
    for (int k = 0; k < BATCH; k++) {
        int i = base + k * NTHREADS;
        if (i < E_old) {
            key[k] = (uint32_t)(src[k] * total_nodes + dst[k]);
            h[k]   = hash_key(key[k]);
            w0[k]  = g_tab[h[k]];
        }
    }
    // Phase C: resolve each insert.
    #pragma unroll
    for (int k = 0; k < BATCH; k++) {
        int i = base + k * NTHREADS;
        if (i >= E_old) continue;
        const unsigned long long word =
            (gen << GEN_SHIFT) | ((unsigned long long)key[k] << KEY_SHIFT)
            | (unsigned long long)(uint32_t)i;
        uint32_t hh = h[k];
        unsigned long long w = w0[k];
        while (true) {
            if ((w >> GEN_SHIFT) != gen) {
                unsigned long long prev = atomicCAS(&g_tab[hh], w, word);
                if (prev == w) break;           // claimed (value rides along)
                w = prev;
            } else if (((w >> KEY_SHIFT) & 0x7FFFFFFull) == key[k]) {
                atomicMax(&g_tab[hh], word);    // duplicate key: max idx wins
                break;
            } else {
                hh = (hh + 1) & TABLE_MASK;
                w = g_tab[hh];
            }
        }
    }
}

// ---- Kernel 2: lookup new edges, gather, emit [E_new, 8] -------------------
__global__ __launch_bounds__(NTHREADS)
void lookup_emit_kernel(const int*   __restrict__ edge_index_new,
                        const float* __restrict__ edge_attr_old,
                        const float* __restrict__ flow_old,
                        const float* __restrict__ edge_attr_new,
                        float*       __restrict__ out,
                        int E_new, int total_nodes) {
    const unsigned long long gen = block_gen(&g_ctr_lkp);
    const int base = blockIdx.x * CHUNK + threadIdx.x;

    int      src[BATCH], dst[BATCH];
    uint32_t key[BATCH], h[BATCH];
    unsigned long long w0[BATCH];
    int      match[BATCH];

    // Phase A: batch coalesced index loads.
    #pragma unroll
    for (int k = 0; k < BATCH; k++) {
        int i = base + k * NTHREADS;
        if (i < E_new) src[k] = __ldg(edge_index_new + i);
    }
    #pragma unroll
    for (int k = 0; k < BATCH; k++) {
        int i = base + k * NTHREADS;
        if (i < E_new) dst[k] = __ldg(edge_index_new + E_new + i);
    }
    // Phase B: keys + batch first-probe loads.
    #pragma unroll
    for (int k = 0; k < BATCH; k++) {
        int i = base + k * NTHREADS;
        if (i < E_new) {
            key[k] = (uint32_t)(src[k] * total_nodes + dst[k]);
            h[k]   = hash_key(key[k]);
            w0[k]  = __ldg(&g_tab[h[k]]);
        }
    }
    // Phase C: resolve probes (expected ~1.2 probes; first already in flight).
    #pragma unroll
    for (int k = 0; k < BATCH; k++) {
        int i = base + k * NTHREADS;
        if (i >= E_new) continue;
        match[k] = -1;
        uint32_t hh = h[k];
        unsigned long long w = w0[k];
        while (true) {
            if ((w >> GEN_SHIFT) != gen) break;               // empty: miss
            if (((w >> KEY_SHIFT) & 0x7FFFFFFull) == key[k]) {
                match[k] = (int)(w & IDX_MASK);
                break;
            }
            hh = (hh + 1) & TABLE_MASK;
            w = __ldg(&g_tab[hh]);
        }
    }
    // Phase D: batch gathers of old feats (independent scattered LDGs).
    float a[BATCH][4];
    #pragma unroll
    for (int k = 0; k < BATCH; k++) {
        int i = base + k * NTHREADS;
        if (i >= E_new) continue;
        if (match[k] >= 0) {
            const float* ea = edge_attr_old + (size_t)match[k] * 3;
            a[k][0] = __ldg(ea + 0);
            a[k][1] = __ldg(ea + 1);
            a[k][2] = __ldg(ea + 2);
            a[k][3] = __ldg(flow_old + match[k]);
        } else {
            a[k][0] = a[k][1] = a[k][2] = a[k][3] = 0.f;
        }
    }
    // Phase E: batch new-attr loads + coalesced float4 stores.
    #pragma unroll
    for (int k = 0; k < BATCH; k++) {
        int i = base + k * NTHREADS;
        if (i >= E_new) continue;
        const float* en = edge_attr_new + (size_t)i * 3;
        float n0 = __ldg(en + 0), n1 = __ldg(en + 1), n2 = __ldg(en + 2);
        float flag = (match[k] >= 0) ? 0.f : 1.f;
        float4* o = reinterpret_cast<float4*>(out + (size_t)i * 8);
        o[0] = make_float4(a[k][0], a[k][1], a[k][2], a[k][3]);
        o[1] = make_float4(n0, n1, n2, flag);
    }
}

extern "C" void kernel_launch(void* const* d_in, const int* in_sizes, int n_in,
                              void* d_out, int out_size) {
    const int*   edge_index_old = (const int*)  d_in[0];
    const float* edge_attr_old  = (const float*)d_in[1];
    const float* flow_old       = (const float*)d_in[2];
    const int*   edge_index_new = (const int*)  d_in[3];
    const float* edge_attr_new  = (const float*)d_in[4];
    (void)n_in; (void)out_size;

    int E_old = in_sizes[1] / 3;   // edge_attr_old is [E_old, 3]
    int E_new = in_sizes[4] / 3;   // edge_attr_new is [E_new, 3]
    int total_nodes = 10000;       // fixed by problem; key fits in 27 bits

    insert_kernel<<<(E_old + CHUNK - 1) / CHUNK, NTHREADS>>>(
        edge_index_old, E_old, total_nodes);
    lookup_emit_kernel<<<(E_new + CHUNK - 1) / CHUNK, NTHREADS>>>(
        edge_index_new, edge_attr_old, flow_old, edge_attr_new,
        (float*)d_out, E_new, total_nodes);
}

// round 10
// speedup vs baseline: 1.6176x; 1.6176x over previous
#include <cuda_runtime.h>
#include <cuda_bf16.h>
#include <cstdint>

// ---------------------------------------------------------------------------
// EdgeAlignmentModule — generation-tagged hash join, 2 launches, no reset.
// R10: back to 1 edge/thread (occupancy >> per-thread MLP at this size) and
// a packed float4 feature table so the lookup gather is ONE scattered LDG.
//
//   key(src,dst) = src * total_nodes + dst   (< 1e8, fits in 27 bits)
//   Slot word (64b) = gen(18) << 46 | key(27) << 19 | idx(19)
//
// Slot with gen field != current gen is EMPTY (stale); claimed by CAS against
// the observed stale word. Duplicate keys within a call -> MAX old index
// (== sequential-scatter "last wins") via atomicMax (equal gen|key orders by
// idx). Per-call gen derived on-device from a per-kernel counter (one bump
// per block; stream ordering partitions arrivals per call). Table starts
// zeroed (gen 0); first call uses gen 1.
// ---------------------------------------------------------------------------

#define TABLE_LOG2 20
#define TABLE_SIZE (1u << TABLE_LOG2)
#define TABLE_MASK (TABLE_SIZE - 1u)

#define GEN_SHIFT 46
#define KEY_SHIFT 19
#define IDX_MASK  ((1u << KEY_SHIFT) - 1u)

#define NTHREADS 256
#define E_OLD_MAX 400000

__device__ unsigned long long g_tab[TABLE_SIZE];   // zero-init: gen 0 = stale
__device__ float4 g_packed[E_OLD_MAX];             // [ea0,ea1,ea2,flow] per old edge
__device__ unsigned long long g_ctr_ins;           // insert call counter
__device__ unsigned long long g_ctr_lkp;           // lookup call counter

__device__ __forceinline__ uint32_t hash_key(uint32_t key) {
    return (key * 0x9E3779B1u) >> (32 - TABLE_LOG2);
}

__device__ __forceinline__ unsigned long long
block_gen(unsigned long long* ctr) {
    __shared__ unsigned long long s_gen;
    if (threadIdx.x == 0) {
        unsigned long long t = atomicAdd(ctr, 1ull);
        s_gen = t / gridDim.x + 1ull;   // same for every block of a call
    }
    __syncthreads();
    return s_gen;
}

// ---- Kernel 1: insert old edges + pack features ----------------------------
__global__ __launch_bounds__(NTHREADS)
void insert_kernel(const int*   __restrict__ edge_index_old,
                   const float* __restrict__ edge_attr_old,
                   const float* __restrict__ flow_old,
                   int E_old, int total_nodes) {
    const unsigned long long gen = block_gen(&g_ctr_ins);
    int i = blockIdx.x * NTHREADS + threadIdx.x;
    if (i >= E_old) return;

    // Issue all independent loads up front (indices + features).
    int src = __ldg(edge_index_old + i);
    int dst = __ldg(edge_index_old + E_old + i);
    const float* ea = edge_attr_old + (size_t)i * 3;
    float f0 = __ldg(ea + 0);
    float f1 = __ldg(ea + 1);
    float f2 = __ldg(ea + 2);
    float f3 = __ldg(flow_old + i);

    // Pack features for single-LDG gather in the lookup kernel.
    g_packed[i] = make_float4(f0, f1, f2, f3);

    uint32_t key = (uint32_t)(src * total_nodes + dst);
    const unsigned long long word =
        (gen << GEN_SHIFT) | ((unsigned long long)key << KEY_SHIFT)
        | (unsigned long long)(uint32_t)i;

    uint32_t h = hash_key(key);
    unsigned long long w = g_tab[h];
    while (true) {
        if ((w >> GEN_SHIFT) != gen) {
            unsigned long long prev = atomicCAS(&g_tab[h], w, word);
            if (prev == w) break;              // claimed (value rides along)
            w = prev;                          // re-examine what beat us
        } else if (((w >> KEY_SHIFT) & 0x7FFFFFFull) == key) {
            atomicMax(&g_tab[h], word);        // duplicate key: max idx wins
            break;
        } else {
            h = (h + 1) & TABLE_MASK;
            w = g_tab[h];
        }
    }
}

// ---- Kernel 2: lookup new edges, gather packed feats, emit [E_new, 8] ------
__global__ __launch_bounds__(NTHREADS)
void lookup_emit_kernel(const int*   __restrict__ edge_index_new,
                        const float* __restrict__ edge_attr_new,
                        float*       __restrict__ out,
                        int E_new, int total_nodes) {
    const unsigned long long gen = block_gen(&g_ctr_lkp);
    int i = blockIdx.x * NTHREADS + threadIdx.x;
    if (i >= E_new) return;

    // Independent loads first: indices + new attrs (coalesced).
    int src = __ldg(edge_index_new + i);
    int dst = __ldg(edge_index_new + E_new + i);
    const float* en = edge_attr_new + (size_t)i * 3;
    float n0 = __ldg(en + 0), n1 = __ldg(en + 1), n2 = __ldg(en + 2);

    uint32_t key = (uint32_t)(src * total_nodes + dst);

    int match = -1;
    uint32_t h = hash_key(key);
    while (true) {
        unsigned long long w = __ldg(&g_tab[h]);
        if ((w >> GEN_SHIFT) != gen) break;                // empty: miss
        if (((w >> KEY_SHIFT) & 0x7FFFFFFull) == key) {
            match = (int)(w & IDX_MASK);
            break;
        }
        h = (h + 1) & TABLE_MASK;
    }

    float4 a = make_float4(0.f, 0.f, 0.f, 0.f);
    float flag = 1.f;  // is_new_edge
    if (match >= 0) {
        a = g_packed[match];                   // ONE scattered 16B gather
        flag = 0.f;
    }

    float4* o = reinterpret_cast<float4*>(out + (size_t)i * 8);
    o[0] = a;
    o[1] = make_float4(n0, n1, n2, flag);
}

extern "C" void kernel_launch(void* const* d_in, const int* in_sizes, int n_in,
                              void* d_out, int out_size) {
    const int*   edge_index_old = (const int*)  d_in[0];
    const float* edge_attr_old  = (const float*)d_in[1];
    const float* flow_old       = (const float*)d_in[2];
    const int*   edge_index_new = (const int*)  d_in[3];
    const float* edge_attr_new  = (const float*)d_in[4];
    (void)n_in; (void)out_size;

    int E_old = in_sizes[1] / 3;   // edge_attr_old is [E_old, 3]
    int E_new = in_sizes[4] / 3;   // edge_attr_new is [E_new, 3]
    int total_nodes = 10000;       // fixed by problem; key fits in 27 bits

    insert_kernel<<<(E_old + NTHREADS - 1) / NTHREADS, NTHREADS>>>(
        edge_index_old, edge_attr_old, flow_old, E_old, total_nodes);
    lookup_emit_kernel<<<(E_new + NTHREADS - 1) / NTHREADS, NTHREADS>>>(
        edge_index_new, edge_attr_new, (float*)d_out, E_new, total_nodes);
}

// round 11
// speedup vs baseline: 1.6333x; 1.0097x over previous
#include <cuda_runtime.h>
#include <cuda_bf16.h>
#include <cstdint>

// ---------------------------------------------------------------------------
// EdgeAlignmentModule — generation-tagged hash join, 2 launches overlapped
// with Programmatic Dependent Launch (PDL).
//
//   key(src,dst) = src * total_nodes + dst   (< 1e8, fits in 27 bits)
//   Slot word (64b) = gen(18) << 46 | key(27) << 19 | idx(19)
//
// Slot with gen field != current gen is EMPTY (stale); claimed by CAS against
// the observed stale word. Duplicate keys within a call -> MAX old index
// (== sequential-scatter "last wins") via atomicMax (equal gen|key orders by
// idx). Per-call gen derived on-device from a per-kernel counter (one bump
// per block; stream ordering partitions arrivals per call). Table starts
// zeroed (gen 0); first call uses gen 1. No reset, no cleanup.
//
// PDL: insert triggers launch-completion at block start, so the lookup grid
// launches immediately and overlaps its independent prologue (index + new-attr
// loads, key computation) with insert. cudaGridDependencySynchronize() gates
// the table probes on insert GRID COMPLETION, so all table atomics are
// visible before any probe. Capturable into CUDA graphs (programmatic edge).
// ---------------------------------------------------------------------------

#define TABLE_LOG2 20
#define TABLE_SIZE (1u << TABLE_LOG2)
#define TABLE_MASK (TABLE_SIZE - 1u)

#define GEN_SHIFT 46
#define KEY_SHIFT 19
#define IDX_MASK  ((1u << KEY_SHIFT) - 1u)

#define NTHREADS 256
#define E_OLD_MAX 400000

__device__ unsigned long long g_tab[TABLE_SIZE];   // zero-init: gen 0 = stale
__device__ float4 g_packed[E_OLD_MAX];             // [ea0,ea1,ea2,flow] per old edge
__device__ unsigned long long g_ctr_ins;           // insert call counter
__device__ unsigned long long g_ctr_lkp;           // lookup call counter

__device__ __forceinline__ uint32_t hash_key(uint32_t key) {
    return (key * 0x9E3779B1u) >> (32 - TABLE_LOG2);
}

__device__ __forceinline__ unsigned long long
block_gen(unsigned long long* ctr) {
    __shared__ unsigned long long s_gen;
    if (threadIdx.x == 0) {
        unsigned long long t = atomicAdd(ctr, 1ull);
        s_gen = t / gridDim.x + 1ull;   // same for every block of a call
    }
    __syncthreads();
    return s_gen;
}

// ---- Kernel 1 (primary): insert old edges + pack features ------------------
__global__ __launch_bounds__(NTHREADS)
void insert_kernel(const int*   __restrict__ edge_index_old,
                   const float* __restrict__ edge_attr_old,
                   const float* __restrict__ flow_old,
                   int E_old, int total_nodes) {
    // Let the dependent (lookup) grid launch NOW; it self-gates on our grid
    // completion before touching g_tab, so triggering early is safe.
    cudaTriggerProgrammaticLaunchCompletion();

    const unsigned long long gen = block_gen(&g_ctr_ins);
    int i = blockIdx.x * NTHREADS + threadIdx.x;
    if (i >= E_old) return;

    // Issue all independent loads up front.
    int src = __ldg(edge_index_old + i);
    int dst = __ldg(edge_index_old + E_old + i);
    const float* ea = edge_attr_old + (size_t)i * 3;
    float f0 = __ldg(ea + 0);
    float f1 = __ldg(ea + 1);
    float f2 = __ldg(ea + 2);
    float f3 = __ldg(flow_old + i);

    // Pack features for single-LDG gather in the lookup kernel.
    g_packed[i] = make_float4(f0, f1, f2, f3);

    uint32_t key = (uint32_t)(src * total_nodes + dst);
    const unsigned long long word =
        (gen << GEN_SHIFT) | ((unsigned long long)key << KEY_SHIFT)
        | (unsigned long long)(uint32_t)i;

    uint32_t h = hash_key(key);
    unsigned long long w = g_tab[h];
    while (true) {
        if ((w >> GEN_SHIFT) != gen) {
            unsigned long long prev = atomicCAS(&g_tab[h], w, word);
            if (prev == w) break;              // claimed (value rides along)
            w = prev;                          // re-examine what beat us
        } else if (((w >> KEY_SHIFT) & 0x7FFFFFFull) == key) {
            atomicMax(&g_tab[h], word);        // duplicate key: max idx wins
            break;
        } else {
            h = (h + 1) & TABLE_MASK;
            w = g_tab[h];
        }
    }
}

// ---- Kernel 2 (dependent): lookup, gather packed feats, emit [E_new, 8] ----
__global__ __launch_bounds__(NTHREADS)
void lookup_emit_kernel(const int*   __restrict__ edge_index_new,
                        const float* __restrict__ edge_attr_new,
                        float*       __restrict__ out,
                        int E_new, int total_nodes) {
    const unsigned long long gen = block_gen(&g_ctr_lkp);
    int i = blockIdx.x * NTHREADS + threadIdx.x;

    // ---- Prologue: everything independent of the hash table ----
    int src = 0, dst = 0;
    float n0 = 0.f, n1 = 0.f, n2 = 0.f;
    if (i < E_new) {
        src = __ldg(edge_index_new + i);
        dst = __ldg(edge_index_new + E_new + i);
        const float* en = edge_attr_new + (size_t)i * 3;
        n0 = __ldg(en + 0); n1 = __ldg(en + 1); n2 = __ldg(en + 2);
    }
    uint32_t key = (uint32_t)(src * total_nodes + dst);
    uint32_t h = hash_key(key);

    // ---- Gate on insert grid completion (table fully built + visible) ----
    cudaGridDependencySynchronize();

    if (i >= E_new) return;

    int match = -1;
    while (true) {
        unsigned long long w = __ldg(&g_tab[h]);
        if ((w >> GEN_SHIFT) != gen) break;                // empty: miss
        if (((w >> KEY_SHIFT) & 0x7FFFFFFull) == key) {
            match = (int)(w & IDX_MASK);
            break;
        }
        h = (h + 1) & TABLE_MASK;
    }

    float4 a = make_float4(0.f, 0.f, 0.f, 0.f);
    float flag = 1.f;  // is_new_edge
    if (match >= 0) {
        a = g_packed[match];                   // ONE scattered 16B gather
        flag = 0.f;
    }

    float4* o = reinterpret_cast<float4*>(out + (size_t)i * 8);
    o[0] = a;
    o[1] = make_float4(n0, n1, n2, flag);
}

extern "C" void kernel_launch(void* const* d_in, const int* in_sizes, int n_in,
                              void* d_out, int out_size) {
    const int*   edge_index_old = (const int*)  d_in[0];
    const float* edge_attr_old  = (const float*)d_in[1];
    const float* flow_old       = (const float*)d_in[2];
    const int*   edge_index_new = (const int*)  d_in[3];
    const float* edge_attr_new  = (const float*)d_in[4];
    (void)n_in; (void)out_size;

    int E_old = in_sizes[1] / 3;   // edge_attr_old is [E_old, 3]
    int E_new = in_sizes[4] / 3;   // edge_attr_new is [E_new, 3]
    int total_nodes = 10000;       // fixed by problem; key fits in 27 bits

    // Primary: plain launch.
    insert_kernel<<<(E_old + NTHREADS - 1) / NTHREADS, NTHREADS>>>(
        edge_index_old, edge_attr_old, flow_old, E_old, total_nodes);

    // Dependent: PDL launch — may start while insert is still running.
    {
        cudaLaunchConfig_t cfg = {};
        cfg.gridDim  = dim3((E_new + NTHREADS - 1) / NTHREADS);
        cfg.blockDim = dim3(NTHREADS);
        cfg.dynamicSmemBytes = 0;
        cfg.stream = 0;   // legacy default stream (same one the harness captures)

        cudaLaunchAttribute attr[1];
        attr[0].id = cudaLaunchAttributeProgrammaticStreamSerialization;
        attr[0].val.programmaticStreamSerializationAllowed = 1;
        cfg.attrs = attr;
        cfg.numAttrs = 1;

        float* out = (float*)d_out;
        cudaLaunchKernelEx(&cfg, lookup_emit_kernel,
                           edge_index_new, edge_attr_new, out,
                           E_new, total_nodes);
    }
}